// round 17
// baseline (speedup 1.0000x reference)
#include <cuda_runtime.h>
#include <cuda_bf16.h>
#include <cstdint>

// Problem constants
#define RR 2048
#define CC 2048
#define DD 64
#define OO 4
#define KP 288            // 256 z-terms + 10 pair + 1 const + 21 zero ; 9 * 32
#define NCHUNK 9          // K chunks of 32

// GEMM tiling: 128x128 CTA, 4 warps of 64x64, 2 CTAs/SM, NO shared memory
#define BM 128
#define BN 128
#define NTHREADS 128

// ---------------------------------------------------------------------------
// Scratch (device globals; no allocation).
//   A/B: pre-packed bf16 tile images (rowoff16): thread (g,tg)'s fragment
//        pair for BOTH k16 groups = ONE uint4 at row*64B + tg*16B
//        (.x/.y = k16 group 0, .z/.w = group 1).
//   g_mask: events packed 32x: bit (c%32) of g_mask[r*64 + c/32] (512 KB,
//        L2-resident) — epilogue reads this instead of cold events DRAM.
// ---------------------------------------------------------------------------
__device__ __nv_bfloat16 g_A[(size_t)16 * NCHUNK * 4096];
__device__ __nv_bfloat16 g_B[(size_t)16 * NCHUNK * 4096];
__device__ uint32_t g_mask[RR * (CC / 32)];

__device__ __forceinline__ int rowoff16(int k) {
    int kk = k & 31;
    int grp = kk >> 4, j = kk & 15;
    int pr = j >> 1, w = j & 1;
    int unit = ((pr & 3) << 2) | (grp << 1) | (pr >> 2);
    return unit * 2 + w;
}

__device__ __forceinline__ size_t idxA(int r, int k) {
    int mt = r >> 7, m = r & 127, ck = k >> 5;
    return ((size_t)(mt * NCHUNK + ck) << 12) + m * 32 + rowoff16(k);
}

__device__ __forceinline__ size_t idxB(int c, int k) {
    int nt = c >> 7, n = c & 127, ck = k >> 5;
    return ((size_t)(nt * NCHUNK + ck) << 12) + n * 32 + rowoff16(k);
}

#define MMA_BF16(c, a0, a1, a2, a3, b0, b1) \
    asm volatile("mma.sync.aligned.m16n8k16.row.col.f32.bf16.bf16.f32 " \
        "{%0,%1,%2,%3}, {%4,%5,%6,%7}, {%8,%9}, {%0,%1,%2,%3};" \
        : "+f"((c)[0]), "+f"((c)[1]), "+f"((c)[2]), "+f"((c)[3]) \
        : "r"(a0), "r"(a1), "r"(a2), "r"(a3), "r"(b0), "r"(b1))

__device__ __forceinline__ float sqrt_ap(float x) {
    float y; asm("sqrt.approx.f32 %0, %1;" : "=f"(y) : "f"(x)); return y;
}
__device__ __forceinline__ float ex2_ap(float x) {
    float y; asm("ex2.approx.f32 %0, %1;" : "=f"(y) : "f"(x)); return y;
}
__device__ __forceinline__ float lg2_ap(float x) {
    float y; asm("lg2.approx.f32 %0, %1;" : "=f"(y) : "f"(x)); return y;
}

// spread 8 bits of x to bit positions 0,4,8,...,28
__device__ __forceinline__ uint32_t spread8(uint32_t x) {
    x = (x | (x << 12)) & 0x000F000Fu;
    x = (x | (x << 6))  & 0x03030303u;
    x = (x | (x << 3))  & 0x11111111u;
    return x;
}

// ---------------------------------------------------------------------------
// Merged prep kernel: 640 blocks x 256 threads.
//   blocks [0,256):   A rows (1 row per warp); block 0 thread 0 zeroes out[0]
//   blocks [256,512): B cols (1 col per warp)
//   blocks [512,640): events -> bitmask (int4 loads + ballots + bit-spread)
// ---------------------------------------------------------------------------
__global__ void prep_all_kernel(const float* __restrict__ z_rows,
                                const float* __restrict__ z_cols,
                                const float* __restrict__ col_times,
                                const int* __restrict__ events,
                                float* __restrict__ out) {
    const int bid  = blockIdx.x;
    const int wid  = threadIdx.x >> 5;
    const int lane = threadIdx.x & 31;

    if (bid == 0 && threadIdx.x == 0) out[0] = 0.0f;

    if (bid < 256) {
        // ---- rows ----
        int r = bid * 8 + wid;
        float z[OO][2];
#pragma unroll
        for (int o = 0; o < OO; o++) {
#pragma unroll
            for (int j = 0; j < 2; j++) {
                int d = lane + j * 32;
                float v = z_rows[((size_t)o * RR + r) * DD + d];
                z[o][j] = v;
                g_A[idxA(r, o * DD + d)] = __float2bfloat16_rn(v);
            }
        }
        int p = 0;
#pragma unroll
        for (int o1 = 0; o1 < OO; o1++) {
#pragma unroll
            for (int o2 = o1; o2 < OO; o2++) {
                float part = z[o1][0] * z[o2][0] + z[o1][1] * z[o2][1];
#pragma unroll
                for (int off = 16; off > 0; off >>= 1)
                    part += __shfl_xor_sync(0xFFFFFFFFu, part, off);
                if (lane == 0) g_A[idxA(r, 256 + p)] = __float2bfloat16_rn(part);
                p++;
            }
        }
        if (lane == 0) g_A[idxA(r, 266)] = __float2bfloat16_rn(1.0f);
        if (lane < 21) g_A[idxA(r, 267 + lane)] = __float2bfloat16_rn(0.0f);
    } else if (bid < 512) {
        // ---- cols ----
        int c = (bid - 256) * 8 + wid;
        float t = col_times[c];
        float coef[OO];
        coef[0] = 1.0f;
        coef[1] = t;
        coef[2] = t * t * 0.5f;
        coef[3] = t * t * t * (1.0f / 6.0f);

        float zc[2];
        float zc2 = 0.0f;
#pragma unroll
        for (int j = 0; j < 2; j++) {
            int d = lane + j * 32;
            zc[j] = z_cols[(size_t)c * DD + d];
            zc2 += zc[j] * zc[j];
        }
#pragma unroll
        for (int off = 16; off > 0; off >>= 1)
            zc2 += __shfl_xor_sync(0xFFFFFFFFu, zc2, off);

#pragma unroll
        for (int o = 0; o < OO; o++) {
#pragma unroll
            for (int j = 0; j < 2; j++) {
                int d = lane + j * 32;
                g_B[idxB(c, o * DD + d)] = __float2bfloat16_rn(-2.0f * coef[o] * zc[j]);
            }
        }
        if (lane == 0) {
            int p = 0;
#pragma unroll
            for (int o1 = 0; o1 < OO; o1++) {
#pragma unroll
                for (int o2 = o1; o2 < OO; o2++) {
                    float f = (o1 == o2) ? 1.0f : 2.0f;
                    g_B[idxB(c, 256 + p)] = __float2bfloat16_rn(f * coef[o1] * coef[o2]);
                    p++;
                }
            }
            g_B[idxB(c, 266)] = __float2bfloat16_rn(zc2);
        }
        if (lane < 21) g_B[idxB(c, 267 + lane)] = __float2bfloat16_rn(0.0f);
    } else {
        // ---- events -> bitmask ----
        // 128 blocks x 8 warps = 1024 warps; each warp packs 4096 ints
        // (128 mask words) in 32 iterations of 128 ints.
        int gw = (bid - 512) * 8 + wid;
        const int4* src = (const int4*)(events + (size_t)gw * 4096);
        uint32_t* dstw = g_mask + gw * 128;
#pragma unroll 8
        for (int i = 0; i < 32; i++) {
            int4 e = src[i * 32 + lane];
            uint32_t b0 = __ballot_sync(0xFFFFFFFFu, e.x != 0);
            uint32_t b1 = __ballot_sync(0xFFFFFFFFu, e.y != 0);
            uint32_t b2 = __ballot_sync(0xFFFFFFFFu, e.z != 0);
            uint32_t b3 = __ballot_sync(0xFFFFFFFFu, e.w != 0);
            if (lane < 4) {
                int sh = lane * 8;     // word `lane` of this 128-int span
                uint32_t w = spread8((b0 >> sh) & 0xFFu)
                           | (spread8((b1 >> sh) & 0xFFu) << 1)
                           | (spread8((b2 >> sh) & 0xFFu) << 2)
                           | (spread8((b3 >> sh) & 0xFFu) << 3);
                dstw[i * 4 + lane] = w;
            }
        }
    }
}

// ---------------------------------------------------------------------------
// bf16 mma.sync GEMM, fragments loaded DIRECTLY from gmem (no smem/barriers),
// + fused log2-domain epilogue with L2-resident bitmask events.
// Chunk 8's second k16 group (k in [272,288)) is zero padding: peeled tail.
// ---------------------------------------------------------------------------
__global__ void __launch_bounds__(NTHREADS, 2)
gemm_mma_kernel(const float* __restrict__ gamma_rows,
                const float* __restrict__ gamma_cols,
                float* __restrict__ out) {
    const int tid  = threadIdx.x;
    const int wid  = tid >> 5;
    const int lane = tid & 31;
    const int wm   = wid >> 1;          // 0..1
    const int wn   = wid & 1;           // 0..1
    const int g    = lane >> 2;         // 0..7
    const int tg   = lane & 3;          // 0..3

    const uint4* __restrict__ paBase = (const uint4*)(
        g_A + ((size_t)(blockIdx.y * NCHUNK) << 12) + (wm * 64 + g) * 32 + tg * 8);
    const uint4* __restrict__ pbBase = (const uint4*)(
        g_B + ((size_t)(blockIdx.x * NCHUNK) << 12) + (wn * 64 + g) * 32 + tg * 8);

    float acc[4][8][4];
#pragma unroll
    for (int mf = 0; mf < 4; mf++)
#pragma unroll
        for (int nf = 0; nf < 8; nf++)
#pragma unroll
            for (int q = 0; q < 4; q++)
                acc[mf][nf][q] = 0.0f;

    // Fully unrolled mainloop (chunks 0..7): 16 independent LDG.128 per chunk
    // feed 64 HMMAs; no syncs anywhere.
#pragma unroll
    for (int ck = 0; ck < NCHUNK - 1; ck++) {
        const uint4* pa = paBase + ck * 512;
        const uint4* pb = pbBase + ck * 512;
        uint4 alo[4], ahi[4], bv[8];
#pragma unroll
        for (int mf = 0; mf < 4; mf++) {
            alo[mf] = __ldg(pa + mf * 64);
            ahi[mf] = __ldg(pa + mf * 64 + 32);
        }
#pragma unroll
        for (int nf = 0; nf < 8; nf++)
            bv[nf] = __ldg(pb + nf * 32);
#pragma unroll
        for (int mf = 0; mf < 4; mf++)
#pragma unroll
            for (int nf = 0; nf < 8; nf++) {
                MMA_BF16(acc[mf][nf], alo[mf].x, ahi[mf].x, alo[mf].y,
                         ahi[mf].y, bv[nf].x, bv[nf].y);
                MMA_BF16(acc[mf][nf], alo[mf].z, ahi[mf].z, alo[mf].w,
                         ahi[mf].w, bv[nf].z, bv[nf].w);
            }
    }

    // ---- tail chunk 8: only first k16 group (second is zero padding) ----
    {
        const uint4* pa = paBase + (NCHUNK - 1) * 512;
        const uint4* pb = pbBase + (NCHUNK - 1) * 512;
        uint4 alo[4], ahi[4], bv[8];
#pragma unroll
        for (int mf = 0; mf < 4; mf++) {
            alo[mf] = __ldg(pa + mf * 64);
            ahi[mf] = __ldg(pa + mf * 64 + 32);
        }
#pragma unroll
        for (int nf = 0; nf < 8; nf++)
            bv[nf] = __ldg(pb + nf * 32);
#pragma unroll
        for (int mf = 0; mf < 4; mf++)
#pragma unroll
            for (int nf = 0; nf < 8; nf++)
                MMA_BF16(acc[mf][nf], alo[mf].x, ahi[mf].x, alo[mf].y,
                         ahi[mf].y, bv[nf].x, bv[nf].y);
    }

    // ---- fused epilogue (log2 domain, bitmask events) ----
    const float L2E = 1.4426950408889634f;
    const float C2  = L2E * L2E;
    const int rbase = blockIdx.y * BM + wm * 64;
    const int cbase = blockIdx.x * BN + wn * 64;
    const int cg0   = cbase >> 5;        // mask word for cols [cbase, +32)

    float accSU = 0.0f, accAB = 0.0f, accLG = 0.0f;
#pragma unroll
    for (int mf = 0; mf < 4; mf++) {
        const int r0 = rbase + mf * 16 + g;
        const float gr0 = gamma_rows[r0] * L2E;
        const float gr1 = gamma_rows[r0 + 8] * L2E;
        // 4 mask words: rows r0 & r0+8, two 32-col halves of the 64-col band
        const uint32_t mA0 = g_mask[r0 * 64 + cg0];
        const uint32_t mA1 = g_mask[r0 * 64 + cg0 + 1];
        const uint32_t mB0 = g_mask[(r0 + 8) * 64 + cg0];
        const uint32_t mB1 = g_mask[(r0 + 8) * 64 + cg0 + 1];
        float prod = 1.0f;
#pragma unroll
        for (int nf = 0; nf < 8; nf++) {
            const int cc = cbase + nf * 8 + tg * 2;
            const float gc0 = gamma_cols[cc] * L2E;
            const float gc1 = gamma_cols[cc + 1] * L2E;
            const uint32_t mr0 = (nf < 4) ? mA0 : mA1;
            const uint32_t mr1 = (nf < 4) ? mB0 : mB1;
            const int b = (nf & 3) * 8 + tg * 2;
            const uint32_t t0 = mr0 >> b;   // bit0: (r0,cc), bit1: (r0,cc+1)
            const uint32_t t1 = mr1 >> b;
            const float* d = acc[mf][nf];
            float gs[4] = {gr0 + gc0, gr0 + gc1, gr1 + gc0, gr1 + gc1};
            uint32_t ev[4] = {t0 & 1u, t0 & 2u, t1 & 1u, t1 & 2u};
#pragma unroll
            for (int q = 0; q < 4; q++) {
                float dd = fmaxf(d[q] * C2, 0.0f);
                float u2 = gs[q] - sqrt_ap(dd);
                float au = fabsf(u2);
                accSU += ev[q] ? u2 : -u2;
                accAB += au;
                float t = ex2_ap(-au);
                prod = fmaf(prod, t, prod);
            }
            if (nf & 1) {                   // one LG2 per 8 elements
                accLG += lg2_ap(prod);
                prod = 1.0f;
            }
        }
    }
    float lsum = 0.69314718056f * (0.5f * (accSU - accAB) - accLG);
#pragma unroll
    for (int off = 16; off > 0; off >>= 1)
        lsum += __shfl_xor_sync(0xFFFFFFFFu, lsum, off);
    if (lane == 0) atomicAdd(out, -lsum);
}

// ---------------------------------------------------------------------------
// launch: TWO kernels
// ---------------------------------------------------------------------------
extern "C" void kernel_launch(void* const* d_in, const int* in_sizes, int n_in,
                              void* d_out, int out_size) {
    const int*   events     = (const int*)d_in[0];
    const float* col_times  = (const float*)d_in[1];
    const float* z_rows     = (const float*)d_in[2];
    const float* z_cols     = (const float*)d_in[3];
    const float* gamma_rows = (const float*)d_in[4];
    const float* gamma_cols = (const float*)d_in[5];
    float* out = (float*)d_out;

    prep_all_kernel<<<640, 256>>>(z_rows, z_cols, col_times, events, out);

    dim3 grid(CC / BN, RR / BM);   // (16, 16)
    gemm_mma_kernel<<<grid, NTHREADS>>>(gamma_rows, gamma_cols, out);
}